// round 3
// baseline (speedup 1.0000x reference)
#include <cuda_runtime.h>
#include <math.h>

// LatentRNN: B=2048, T=512, P=8, L=64, H=180
// 128 persistent CTAs x 16 batch rows. All state in SMEM. SMEM-staged
// double-buffered weight tiles + fma.rn.f32x2 packed math.

#define B_    2048
#define T_    512
#define P_    8
#define L_    64
#define H_    180
#define IN_K  72
#define CAT_K 244
#define BT    16
#define NTHR  384
#define KT    36
#define WS    37

typedef unsigned long long ull;

struct __align__(16) Smem {
    float inT[IN_K][BT];       // [phys_t ; cur] transposed
    float xT [H_][BT];         // gelu(in @ W_in^T)
    float hT [2][H_][BT];      // hidden state, double buffered
    float giT[3*H_][BT];       // x @ W_ih^T (+ alias: catT rows 0..243)
    float ghT[3*H_][BT];       // h @ W_hh^T (+ alias: oT rows 0..179)
    float cur[BT][L_];         // current latents
    float Wt [2][360*WS];      // double-buffered staged weight tiles
};

__device__ __forceinline__ float gelu_f(float v) {
    return 0.5f * v * (1.0f + erff(v * 0.70710678118654752440f));
}
__device__ __forceinline__ float sigmoid_f(float v) {
    return 1.0f / (1.0f + expf(-v));
}
__device__ __forceinline__ void ffma2(ull& d, ull a, ull b) {
    asm("fma.rn.f32x2 %0, %1, %2, %0;" : "+l"(d) : "l"(a), "l"(b));
}
__device__ __forceinline__ ull packw(float w) {
    ull r; unsigned u = __float_as_uint(w);
    asm("mov.b64 %0, {%1, %1};" : "=l"(r) : "r"(u));
    return r;
}
__device__ __forceinline__ float2 unpack(ull v) {
    float2 f;
    asm("mov.b64 {%0, %1}, %2;" : "=f"(f.x), "=f"(f.y) : "l"(v));
    return f;
}

// Stage one K-tile of a single weight matrix [NCOLS x K] into Wt[buf].
template<int NCOLS, int K>
__device__ __forceinline__ void stage(Smem* s, const float* __restrict__ W,
                                      int kt, int buf, int tid) {
    const int k0   = kt * KT;
    const int klen = (K - k0 < KT) ? (K - k0) : KT;
    const int f4   = klen >> 2;
    const int total = NCOLS * f4;
    for (int i = tid; i < total; i += NTHR) {
        int r = i / f4, c = i - r * f4;
        const float4 v = *(const float4*)(W + r * K + k0 + c * 4);
        float* d = &s->Wt[buf][r * WS + c * 4];
        d[0] = v.x; d[1] = v.y; d[2] = v.z; d[3] = v.w;
    }
}

// Generic staged GEMM: outT[j][r] = (gelu?)(sum_k act[k][r] * W[j][k] + bias[j])
// Thread task = (col group of NC, row quarter of 4). NR fixed at 4 rows (2 f32x2).
template<int NCOLS, int NC, int K, bool GELU>
__device__ void gemm_phase(Smem* s, const float* __restrict__ W,
                           const float* __restrict__ bias,
                           const float (*__restrict__ act)[BT],
                           float (*__restrict__ outT)[BT], int tid) {
    constexpr int NTASK = (NCOLS / NC) * 4;
    constexpr int NT = (K + KT - 1) / KT;
    const int cg = tid >> 2, q = tid & 3;
    const int col0 = cg * NC, rowoff = q * 4;
    const bool on = tid < NTASK;
    ull acc[2 * NC];
#pragma unroll
    for (int i = 0; i < 2 * NC; i++) acc[i] = 0ull;

    stage<NCOLS, K>(s, W, 0, 0, tid);
    __syncthreads();
    for (int kt = 0; kt < NT; kt++) {
        if (kt + 1 < NT) stage<NCOLS, K>(s, W, kt + 1, (kt + 1) & 1, tid);
        if (on) {
            const int k0 = kt * KT;
            const int klen = (K - k0 < KT) ? (K - k0) : KT;
            const float* wr = &s->Wt[kt & 1][col0 * WS];
            if (klen == KT) {
#pragma unroll 6
                for (int k = 0; k < KT; k++) {
                    ulonglong2 a = *(const ulonglong2*)&act[k0 + k][rowoff];
#pragma unroll
                    for (int c = 0; c < NC; c++) {
                        ull w2 = packw(wr[c * WS + k]);
                        ffma2(acc[2 * c],     a.x, w2);
                        ffma2(acc[2 * c + 1], a.y, w2);
                    }
                }
            } else {
                for (int k = 0; k < klen; k++) {
                    ulonglong2 a = *(const ulonglong2*)&act[k0 + k][rowoff];
#pragma unroll
                    for (int c = 0; c < NC; c++) {
                        ull w2 = packw(wr[c * WS + k]);
                        ffma2(acc[2 * c],     a.x, w2);
                        ffma2(acc[2 * c + 1], a.y, w2);
                    }
                }
            }
        }
        __syncthreads();
    }
    if (on) {
#pragma unroll
        for (int c = 0; c < NC; c++) {
            float bb = bias[col0 + c];
#pragma unroll
            for (int i = 0; i < 2; i++) {
                float2 f = unpack(acc[2 * c + i]);
                f.x += bb; f.y += bb;
                if (GELU) { f.x = gelu_f(f.x); f.y = gelu_f(f.y); }
                *(float2*)&outT[col0 + c][rowoff + 2 * i] = f;
            }
        }
    }
}

// Stage for the fused gi/gh GEMM: 360-column block p of the 1080 virtual cols
// (0..539 -> W_ih rows, 540..1079 -> W_hh rows).
__device__ __forceinline__ void stageC(Smem* s, const float* __restrict__ W_ih,
                                       const float* __restrict__ W_hh,
                                       int p, int kt, int buf, int tid) {
    const int k0 = kt * KT;
    for (int i = tid; i < 360 * 9; i += NTHR) {
        int r = i / 9, c = i - r * 9;
        int g = p * 360 + r;
        const float* src = (g < 540) ? (W_ih + g * H_ + k0 + c * 4)
                                     : (W_hh + (g - 540) * H_ + k0 + c * 4);
        float4 v = *(const float4*)src;
        float* d = &s->Wt[buf][r * WS + c * 4];
        d[0] = v.x; d[1] = v.y; d[2] = v.z; d[3] = v.w;
    }
}

// Phase C: gi = x @ W_ih^T + b_ih ; gh = h @ W_hh^T + b_hh. 1080 cols, 3 passes.
__device__ void phaseC(Smem* s, const float* __restrict__ W_ih,
                       const float* __restrict__ W_hh,
                       const float* __restrict__ b_ih,
                       const float* __restrict__ b_hh, int cb, int tid) {
    const int cg = tid >> 2, q = tid & 3, rowoff = q * 4;
    const bool on = tid < 360;
    for (int p = 0; p < 3; p++) {
        const int g0 = p * 360 + cg * 4;          // group never straddles 540 (540%4==0)
        const float (*act)[BT] = (g0 < 540) ? (const float (*)[BT])s->xT
                                            : (const float (*)[BT])s->hT[cb];
        ull acc[8];
#pragma unroll
        for (int i = 0; i < 8; i++) acc[i] = 0ull;

        stageC(s, W_ih, W_hh, p, 0, 0, tid);
        __syncthreads();
        for (int kt = 0; kt < 5; kt++) {
            if (kt < 4) stageC(s, W_ih, W_hh, p, kt + 1, (kt + 1) & 1, tid);
            if (on) {
                const int k0 = kt * KT;
                const float* wr = &s->Wt[kt & 1][(cg * 4) * WS];
#pragma unroll 6
                for (int k = 0; k < KT; k++) {
                    ulonglong2 a = *(const ulonglong2*)&act[k0 + k][rowoff];
#pragma unroll
                    for (int c = 0; c < 4; c++) {
                        ull w2 = packw(wr[c * WS + k]);
                        ffma2(acc[2 * c],     a.x, w2);
                        ffma2(acc[2 * c + 1], a.y, w2);
                    }
                }
            }
            __syncthreads();
        }
        if (on) {
#pragma unroll
            for (int c = 0; c < 4; c++) {
                int g = g0 + c;
                float bb; float* orow;
                if (g < 540) { bb = b_ih[g];       orow = s->giT[g]; }
                else         { bb = b_hh[g - 540]; orow = s->ghT[g - 540]; }
#pragma unroll
                for (int i = 0; i < 2; i++) {
                    float2 f = unpack(acc[2 * c + i]);
                    f.x += bb; f.y += bb;
                    *(float2*)&orow[rowoff + 2 * i] = f;
                }
            }
        }
    }
}

// Phase E: delta = oT @ W_o2^T + b_o2 ; cur = clip(cur + delta); store out.
__device__ void phaseE(Smem* s, const float* __restrict__ W_o2,
                       const float* __restrict__ b_o2,
                       float* __restrict__ out, int b0, int t, int tid) {
    const int j = tid & 63, q = tid >> 6;    // q<4 for tid<256
    const bool on = tid < 256;
    const int rowoff = q * 4;
    ull acc[2] = {0ull, 0ull};

    stage<L_, H_>(s, W_o2, 0, 0, tid);
    __syncthreads();
    for (int kt = 0; kt < 5; kt++) {
        if (kt < 4) stage<L_, H_>(s, W_o2, kt + 1, (kt + 1) & 1, tid);
        if (on) {
            const int k0 = kt * KT;
            const float* wr = &s->Wt[kt & 1][j * WS];
#pragma unroll 6
            for (int k = 0; k < KT; k++) {
                ulonglong2 a = *(const ulonglong2*)&s->ghT[k0 + k][rowoff]; // oT alias
                ull w2 = packw(wr[k]);
                ffma2(acc[0], a.x, w2);
                ffma2(acc[1], a.y, w2);
            }
        }
        __syncthreads();
    }
    if (on) {
        float bb = b_o2[j];
#pragma unroll
        for (int i = 0; i < 2; i++) {
            float2 f = unpack(acc[i]);
            int r0 = rowoff + 2 * i;
            float c0 = fminf(fmaxf(s->cur[r0][j]     + f.x + bb, 0.f), 1.f);
            float c1 = fminf(fmaxf(s->cur[r0 + 1][j] + f.y + bb, 0.f), 1.f);
            s->cur[r0][j] = c0; s->cur[r0 + 1][j] = c1;
            out[((size_t)(b0 + r0) * T_ + t) * L_ + j]     = c0;
            out[((size_t)(b0 + r0 + 1) * T_ + t) * L_ + j] = c1;
        }
    }
}

// Simple fp32 col-GEMM for the one-time h0 projection.
__device__ __forceinline__ void colgemm(const float* __restrict__ w, int K,
                                        const float (*__restrict__ in)[BT],
                                        float* __restrict__ acc) {
#pragma unroll 4
    for (int k = 0; k < K; k += 4) {
        float4 wv = *(const float4*)(w + k);
        float wa[4] = {wv.x, wv.y, wv.z, wv.w};
#pragma unroll
        for (int kk = 0; kk < 4; kk++) {
            const float4* xr = (const float4*)(in[k + kk]);
            float4 a = xr[0], b = xr[1], c = xr[2], d = xr[3];
            float w0 = wa[kk];
            acc[0]  += a.x * w0; acc[1]  += a.y * w0; acc[2]  += a.z * w0; acc[3]  += a.w * w0;
            acc[4]  += b.x * w0; acc[5]  += b.y * w0; acc[6]  += b.z * w0; acc[7]  += b.w * w0;
            acc[8]  += c.x * w0; acc[9]  += c.y * w0; acc[10] += c.z * w0; acc[11] += c.w * w0;
            acc[12] += d.x * w0; acc[13] += d.y * w0; acc[14] += d.z * w0; acc[15] += d.w * w0;
        }
    }
}

__global__ __launch_bounds__(NTHR, 1)
void latent_rnn_kernel(const float* __restrict__ phys,
                       const float* __restrict__ latents,
                       const float* __restrict__ W_in, const float* __restrict__ b_in,
                       const float* __restrict__ W_hp, const float* __restrict__ b_hp,
                       const float* __restrict__ W_ih, const float* __restrict__ b_ih,
                       const float* __restrict__ W_hh, const float* __restrict__ b_hh,
                       const float* __restrict__ W_o1, const float* __restrict__ b_o1,
                       const float* __restrict__ W_o2, const float* __restrict__ b_o2,
                       float* __restrict__ out)
{
    extern __shared__ char smem_raw[];
    Smem* s = reinterpret_cast<Smem*>(smem_raw);
    const int tid = threadIdx.x;
    const int b0  = blockIdx.x * BT;

    // init: cur = latents; stage latents^T for h0 GEMM
    for (int i = tid; i < BT * L_; i += NTHR) {
        int r = i >> 6, l = i & 63;
        float v = latents[(b0 + r) * L_ + l];
        s->cur[r][l] = v;
        s->inT[l][r] = v;
    }
    __syncthreads();

    // h0 = latents @ W_hp^T + b_hp (once — plain fp32 path)
    for (int j = tid; j < H_; j += NTHR) {
        float acc[BT];
#pragma unroll
        for (int r = 0; r < BT; r++) acc[r] = 0.f;
        colgemm(W_hp + j * L_, L_, (const float (*)[BT])s->inT, acc);
        float bb = b_hp[j];
#pragma unroll
        for (int r = 0; r < BT; r++) s->hT[0][j][r] = acc[r] + bb;
    }

    for (int t = 0; t < T_; t++) {
        const int cb = t & 1, nb = cb ^ 1;
        __syncthreads();   // prev E epilogue (cur) -> A; also h0 -> first A

        // A: inT = [phys_t ; cur] transposed
        for (int i = tid; i < BT * IN_K; i += NTHR) {
            int r = i / IN_K, k = i - r * IN_K;
            s->inT[k][r] = (k < P_) ? phys[((size_t)(b0 + r) * T_ + t) * P_ + k]
                                    : s->cur[r][k - P_];
        }
        // B: xT = gelu(inT @ W_in^T + b_in)   (A-writes ordered by B's first sync)
        gemm_phase<H_, 2, IN_K, true>(s, W_in, b_in,
                                      (const float (*)[BT])s->inT, s->xT, tid);
        // C: gi/gh GEMMs
        phaseC(s, W_ih, W_hh, b_ih, b_hh, cb, tid);
        __syncthreads();   // C epilogue -> gates

        // gates: h_new; catT[j] (alias giT[j]) = h_new
        for (int i = tid; i < H_ * BT; i += NTHR) {
            int j = i >> 4, r = i & 15;
            float rg = sigmoid_f(s->giT[j][r] + s->ghT[j][r]);
            float zg = sigmoid_f(s->giT[j + H_][r] + s->ghT[j + H_][r]);
            float ng = tanhf(s->giT[j + 2 * H_][r] + rg * s->ghT[j + 2 * H_][r]);
            float hn = (1.f - zg) * ng + zg * s->hT[cb][j][r];
            s->hT[nb][j][r] = hn;
            s->giT[j][r] = hn;      // read-before-write, element owned by this thread
        }
        __syncthreads();   // z-rows of giT fully consumed before cur-copy aliases them

        // catT[H..H+L) = cur
        for (int i = tid; i < L_ * BT; i += NTHR) {
            int l = i >> 4, r = i & 15;
            s->giT[H_ + l][r] = s->cur[r][l];
        }
        // D: oT (alias ghT) = gelu(catT @ W_o1^T + b_o1)
        gemm_phase<H_, 2, CAT_K, true>(s, W_o1, b_o1,
                                       (const float (*)[BT])s->giT, s->ghT, tid);
        // E: cur update + output store
        phaseE(s, W_o2, b_o2, out, b0, t, tid);
    }
}

extern "C" void kernel_launch(void* const* d_in, const int* in_sizes, int n_in,
                              void* d_out, int out_size)
{
    const float* phys    = (const float*)d_in[0];
    const float* latents = (const float*)d_in[1];
    const float* W_in    = (const float*)d_in[2];
    const float* b_in    = (const float*)d_in[3];
    const float* W_hp    = (const float*)d_in[4];
    const float* b_hp    = (const float*)d_in[5];
    const float* W_ih    = (const float*)d_in[6];
    const float* b_ih    = (const float*)d_in[7];
    const float* W_hh    = (const float*)d_in[8];
    const float* b_hh    = (const float*)d_in[9];
    const float* W_o1    = (const float*)d_in[10];
    const float* b_o1    = (const float*)d_in[11];
    const float* W_o2    = (const float*)d_in[12];
    const float* b_o2    = (const float*)d_in[13];
    float* out = (float*)d_out;

    static bool attr_set = false;
    if (!attr_set) {
        cudaFuncSetAttribute(latent_rnn_kernel,
                             cudaFuncAttributeMaxDynamicSharedMemorySize,
                             (int)sizeof(Smem));
        attr_set = true;
    }

    latent_rnn_kernel<<<B_ / BT, NTHR, sizeof(Smem)>>>(
        phys, latents, W_in, b_in, W_hp, b_hp, W_ih, b_ih, W_hh, b_hh,
        W_o1, b_o1, W_o2, b_o2, out);
}